// round 2
// baseline (speedup 1.0000x reference)
#include <cuda_runtime.h>
#include <cstddef>

#define POOL 7
#define VOX  343          // 7*7*7
#define NCH  64
#define CG_SZ 16          // channels per block (gridDim.y = 4)

__global__ __launch_bounds__(352)
void roi_pool_kernel(const float* __restrict__ x0, const float* __restrict__ x1,
                     const float* __restrict__ x2, const float* __restrict__ x3,
                     const float* __restrict__ boxes, float* __restrict__ out,
                     int nb /* rois per batch */)
{
    const int roi = blockIdx.x;
    const int cg  = blockIdx.y;          // channel group 0..3
    const int t   = threadIdx.x;

    __shared__ int   s_cnt[3][POOL];
    __shared__ int   s_idx[3][POOL][4];  // premultiplied element offsets
    __shared__ float s_w  [3][POOL][4];
    __shared__ const float* s_base;      // feat + b*C*spat
    __shared__ int s_spat;

    if (t < 21) {
        const int d   = t / POOL;        // 0=z (depth), 1=y, 2=x
        const int bin = t % POOL;
        const float* bp = boxes + (size_t)roi * 6;
        const float b0 = bp[0], b1 = bp[1], b2 = bp[2];
        const float b3 = bp[3], b4 = bp[4], b5 = bp[5];

        // FPN level (match reference rounding; only floor() is discontinuous)
        const float area = (b3 - b0 + 1.0f) * (b4 - b1 + 1.0f) * (b5 - b2 + 1.0f);
        const float s    = sqrtf(area);
        float lf = floorf(4.0f + log2f(s / 224.0f + 1e-6f));
        lf = fminf(fmaxf(lf, 2.0f), 5.0f);
        const int L = (int)lf - 2;                    // 0..3
        const float scale = 0.25f / (float)(1 << L);  // exact powers of two
        const int   dim   = 40 >> L;
        const float dimf  = (float)dim;

        const float loC = __fmul_rn((d == 0 ? b0 : (d == 1 ? b1 : b2)), scale);
        const float hiC = __fmul_rn((d == 0 ? b3 : (d == 1 ? b4 : b5)), scale);
        const float len    = fmaxf(__fadd_rn(hiC, -loC), 1.0f);
        const float bin_sz = __fdiv_rn(len, 7.0f);
        const int   mult   = (d == 0) ? dim * dim : (d == 1 ? dim : 1);

        int   ids[4];
        float ws[4];
        int n = 0;
        #pragma unroll
        for (int smp = 0; smp < 2; ++smp) {
            const float pos = ((float)(2 * bin + smp) + 0.5f) * 0.5f;   // exact
            float c = __fadd_rn(loC, __fmul_rn(pos, bin_sz));
            const float valid = (c > -1.0f && c < dimf) ? 1.0f : 0.0f;
            c = fminf(fmaxf(c, 0.0f), dimf - 1.0f);
            const float low = floorf(c);
            const int   li  = (int)low;
            const int   hi  = min(li + 1, dim - 1);
            const float fr  = c - low;
            const float w_hi = fr * valid;
            const float w_lo = (1.0f - fr) * valid;

            int   pi[2] = {li, hi};
            float pw[2] = {w_lo, w_hi};
            #pragma unroll
            for (int q = 0; q < 2; ++q) {
                if (pw[q] == 0.0f) continue;       // dropping exact zeros is value-neutral
                bool found = false;
                for (int k = 0; k < n; ++k)
                    if (ids[k] == pi[q]) { ws[k] += pw[q]; found = true; break; }
                if (!found) { ids[n] = pi[q]; ws[n] = pw[q]; ++n; }
            }
        }
        s_cnt[d][bin] = n;
        #pragma unroll
        for (int k = 0; k < 4; ++k) {
            s_idx[d][bin][k] = (k < n) ? ids[k] * mult : 0;
            s_w  [d][bin][k] = (k < n) ? ws[k]         : 0.0f;
        }

        if (t == 0) {
            const float* f = (L == 0) ? x0 : (L == 1) ? x1 : (L == 2) ? x2 : x3;
            const int spat = dim * dim * dim;
            const int b    = roi / nb;
            s_base = f + (size_t)b * NCH * spat;
            s_spat = spat;
        }
    }
    __syncthreads();

    if (t >= VOX) return;

    const int px = t % 7;
    const int py = (t / 7) % 7;
    const int pz = t / 49;

    // Load tap tables into registers (static indexing)
    int   zo[4], yo[4], xo[4];
    float zw[4], yw[4], xw[4];
    #pragma unroll
    for (int k = 0; k < 4; ++k) {
        zo[k] = s_idx[0][pz][k]; zw[k] = s_w[0][pz][k];
        yo[k] = s_idx[1][py][k]; yw[k] = s_w[1][py][k];
        xo[k] = s_idx[2][px][k]; xw[k] = s_w[2][px][k];
    }
    const int nz = s_cnt[0][pz];
    const int ny = s_cnt[1][py];
    const int nx = s_cnt[2][px];

    const int spat = s_spat;
    const float* __restrict__ base = s_base + (size_t)(cg * CG_SZ) * spat;
    float* __restrict__ op = out + ((size_t)roi * NCH + (size_t)cg * CG_SZ) * VOX + t;

    #pragma unroll 2
    for (int cc = 0; cc < CG_SZ; ++cc) {
        const float* __restrict__ p = base + (size_t)cc * spat;
        float acc = 0.0f;
        #pragma unroll
        for (int iz = 0; iz < 4; ++iz) {
            if (iz >= nz) break;
            const float* pzp = p + zo[iz];
            const float wzv  = zw[iz];
            #pragma unroll
            for (int iy = 0; iy < 4; ++iy) {
                if (iy >= ny) break;
                const float* pyp = pzp + yo[iy];
                const float wzy  = wzv * yw[iy];
                float sx = 0.0f;
                #pragma unroll
                for (int ix = 0; ix < 4; ++ix) {
                    if (ix >= nx) break;
                    sx = fmaf(xw[ix], __ldg(pyp + xo[ix]), sx);
                }
                acc = fmaf(wzy, sx, acc);
            }
        }
        op[(size_t)cc * VOX] = acc * 0.125f;   // mean over 2x2x2 samples
    }
}

extern "C" void kernel_launch(void* const* d_in, const int* in_sizes, int n_in,
                              void* d_out, int out_size)
{
    const float* x0    = (const float*)d_in[0];
    const float* x1    = (const float*)d_in[1];
    const float* x2    = (const float*)d_in[2];
    const float* x3    = (const float*)d_in[3];
    const float* boxes = (const float*)d_in[4];
    float* out = (float*)d_out;

    const int nrois = in_sizes[4] / 6;                 // B * nb (=256)
    int B = in_sizes[0] / (NCH * 40 * 40 * 40);
    if (B < 1) B = 1;
    int nb = nrois / B;
    if (nb < 1) nb = 1;

    dim3 grid(nrois, NCH / CG_SZ);
    roi_pool_kernel<<<grid, 352>>>(x0, x1, x2, x3, boxes, out, nb);
}

// round 6
// speedup vs baseline: 8.8789x; 8.8789x over previous
#include <cuda_runtime.h>
#include <cstddef>

#define POOL 7
#define VOX  343          // 7*7*7
#define NCH  64
#define CG_SZ 16          // channels per block (gridDim.y = 4)

__global__ __launch_bounds__(352)
void roi_pool_kernel(const float* __restrict__ x0, const float* __restrict__ x1,
                     const float* __restrict__ x2, const float* __restrict__ x3,
                     const float* __restrict__ boxes, float* __restrict__ out,
                     int nb /* rois per batch */)
{
    const int roi = blockIdx.x;
    const int cg  = blockIdx.y;          // channel group 0..3
    const int t   = threadIdx.x;

    __shared__ int   s_cnt[3][POOL];
    __shared__ int   s_idx[3][POOL][4];  // premultiplied element offsets
    __shared__ float s_w  [3][POOL][4];
    __shared__ const float* s_base;      // feat + b*C*spat
    __shared__ int s_spat;

    if (t < 21) {
        const int d   = t / POOL;        // 0=z (depth), 1=y, 2=x
        const int bin = t % POOL;
        const float* bp = boxes + (size_t)roi * 6;
        const float b0 = bp[0], b1 = bp[1], b2 = bp[2];
        const float b3 = bp[3], b4 = bp[4], b5 = bp[5];

        // FPN level (match reference rounding; only floor() is discontinuous)
        const float area = (b3 - b0 + 1.0f) * (b4 - b1 + 1.0f) * (b5 - b2 + 1.0f);
        const float s    = sqrtf(area);
        float lf = floorf(4.0f + log2f(s / 224.0f + 1e-6f));
        lf = fminf(fmaxf(lf, 2.0f), 5.0f);
        const int L = (int)lf - 2;                    // 0..3
        const float scale = 0.25f / (float)(1 << L);  // exact powers of two
        const int   dim   = 40 >> L;
        const float dimf  = (float)dim;

        const float loC = __fmul_rn((d == 0 ? b0 : (d == 1 ? b1 : b2)), scale);
        const float hiC = __fmul_rn((d == 0 ? b3 : (d == 1 ? b4 : b5)), scale);
        const float len    = fmaxf(__fadd_rn(hiC, -loC), 1.0f);
        const float bin_sz = __fdiv_rn(len, 7.0f);
        const int   mult   = (d == 0) ? dim * dim : (d == 1 ? dim : 1);

        int   ids[4];
        float ws[4];
        int n = 0;
        #pragma unroll
        for (int smp = 0; smp < 2; ++smp) {
            const float pos = ((float)(2 * bin + smp) + 0.5f) * 0.5f;   // exact
            float c = __fadd_rn(loC, __fmul_rn(pos, bin_sz));
            const float valid = (c > -1.0f && c < dimf) ? 1.0f : 0.0f;
            c = fminf(fmaxf(c, 0.0f), dimf - 1.0f);
            const float low = floorf(c);
            const int   li  = (int)low;
            const int   hi  = min(li + 1, dim - 1);
            const float fr  = c - low;
            const float w_hi = fr * valid;
            const float w_lo = (1.0f - fr) * valid;

            int   pi[2] = {li, hi};
            float pw[2] = {w_lo, w_hi};
            #pragma unroll
            for (int q = 0; q < 2; ++q) {
                if (pw[q] == 0.0f) continue;       // dropping exact zeros is value-neutral
                bool found = false;
                for (int k = 0; k < n; ++k)
                    if (ids[k] == pi[q]) { ws[k] += pw[q]; found = true; break; }
                if (!found) { ids[n] = pi[q]; ws[n] = pw[q]; ++n; }
            }
        }
        s_cnt[d][bin] = n;
        #pragma unroll
        for (int k = 0; k < 4; ++k) {
            s_idx[d][bin][k] = (k < n) ? ids[k] * mult : 0;
            s_w  [d][bin][k] = (k < n) ? ws[k]         : 0.0f;
        }

        if (t == 0) {
            const float* f = (L == 0) ? x0 : (L == 1) ? x1 : (L == 2) ? x2 : x3;
            const int spat = dim * dim * dim;
            const int b    = roi / nb;
            s_base = f + (size_t)b * NCH * spat;
            s_spat = spat;
        }
    }
    __syncthreads();

    if (t >= VOX) return;

    const int px = t % 7;
    const int py = (t / 7) % 7;
    const int pz = t / 49;

    // Load tap tables into registers (static indexing)
    int   zo[4], yo[4], xo[4];
    float zw[4], yw[4], xw[4];
    #pragma unroll
    for (int k = 0; k < 4; ++k) {
        zo[k] = s_idx[0][pz][k]; zw[k] = s_w[0][pz][k];
        yo[k] = s_idx[1][py][k]; yw[k] = s_w[1][py][k];
        xo[k] = s_idx[2][px][k]; xw[k] = s_w[2][px][k];
    }
    const int nz = s_cnt[0][pz];
    const int ny = s_cnt[1][py];
    const int nx = s_cnt[2][px];

    const int spat  = s_spat;
    const int spat2 = spat + spat;
    const int spat3 = spat2 + spat;
    const float* __restrict__ base = s_base + (size_t)(cg * CG_SZ) * spat;
    float* __restrict__ op = out + ((size_t)roi * NCH + (size_t)cg * CG_SZ) * VOX + t;

    // 4 channels at a time: identical tap addresses, 4 independent load/FMA
    // streams -> MLP x4 vs. one channel at a time.
    #pragma unroll 1
    for (int cc = 0; cc < CG_SZ; cc += 4) {
        const float* __restrict__ p = base + (size_t)cc * spat;
        float a0 = 0.0f, a1 = 0.0f, a2 = 0.0f, a3 = 0.0f;
        #pragma unroll
        for (int iz = 0; iz < 4; ++iz) {
            if (iz >= nz) break;
            const float* pzp = p + zo[iz];
            const float wzv  = zw[iz];
            #pragma unroll
            for (int iy = 0; iy < 4; ++iy) {
                if (iy >= ny) break;
                const float* pyp = pzp + yo[iy];
                const float wzy  = wzv * yw[iy];
                float s0 = 0.0f, s1 = 0.0f, s2 = 0.0f, s3 = 0.0f;
                #pragma unroll
                for (int ix = 0; ix < 4; ++ix) {
                    if (ix >= nx) break;
                    const float* q = pyp + xo[ix];
                    const float w  = xw[ix];
                    const float v0 = __ldg(q);
                    const float v1 = __ldg(q + spat);
                    const float v2 = __ldg(q + spat2);
                    const float v3 = __ldg(q + spat3);
                    s0 = fmaf(w, v0, s0);
                    s1 = fmaf(w, v1, s1);
                    s2 = fmaf(w, v2, s2);
                    s3 = fmaf(w, v3, s3);
                }
                a0 = fmaf(wzy, s0, a0);
                a1 = fmaf(wzy, s1, a1);
                a2 = fmaf(wzy, s2, a2);
                a3 = fmaf(wzy, s3, a3);
            }
        }
        float* o = op + (size_t)cc * VOX;
        o[0]               = a0 * 0.125f;   // mean over 2x2x2 samples
        o[(size_t)VOX]     = a1 * 0.125f;
        o[(size_t)VOX * 2] = a2 * 0.125f;
        o[(size_t)VOX * 3] = a3 * 0.125f;
    }
}

extern "C" void kernel_launch(void* const* d_in, const int* in_sizes, int n_in,
                              void* d_out, int out_size)
{
    const float* x0    = (const float*)d_in[0];
    const float* x1    = (const float*)d_in[1];
    const float* x2    = (const float*)d_in[2];
    const float* x3    = (const float*)d_in[3];
    const float* boxes = (const float*)d_in[4];
    float* out = (float*)d_out;

    const int nrois = in_sizes[4] / 6;                 // B * nb (=256)
    int B = in_sizes[0] / (NCH * 40 * 40 * 40);
    if (B < 1) B = 1;
    int nb = nrois / B;
    if (nb < 1) nb = 1;

    dim3 grid(nrois, NCH / CG_SZ);
    roi_pool_kernel<<<grid, 352>>>(x0, x1, x2, x3, boxes, out, nb);
}

// round 13
// speedup vs baseline: 11.0752x; 1.2474x over previous
#include <cuda_runtime.h>
#include <cstddef>

#define POOL 7
#define VOX  343          // 7*7*7
#define NCH  64
#define CG_SZ 16          // channels per block (gridDim.y = 4)

__global__ __launch_bounds__(352, 3)
void roi_pool_kernel(const float* __restrict__ x0, const float* __restrict__ x1,
                     const float* __restrict__ x2, const float* __restrict__ x3,
                     const float* __restrict__ boxes, float* __restrict__ out,
                     int nb /* rois per batch */)
{
    const int roi = blockIdx.x;
    const int cg  = blockIdx.y;          // channel group 0..3
    const int t   = threadIdx.x;

    __shared__ int   s_cnt[3][POOL];
    __shared__ int   s_idx[3][POOL][4];  // premultiplied element offsets
    __shared__ float s_w  [3][POOL][4];
    __shared__ const float* s_base;      // feat + b*C*spat
    __shared__ int s_lvl;

    if (t < 21) {
        const int d   = t / POOL;        // 0=z (depth), 1=y, 2=x
        const int bin = t % POOL;
        const float* bp = boxes + (size_t)roi * 6;
        const float b0 = bp[0], b1 = bp[1], b2 = bp[2];
        const float b3 = bp[3], b4 = bp[4], b5 = bp[5];

        // FPN level (match reference rounding; only floor() is discontinuous)
        const float area = (b3 - b0 + 1.0f) * (b4 - b1 + 1.0f) * (b5 - b2 + 1.0f);
        const float s    = sqrtf(area);
        float lf = floorf(4.0f + log2f(s / 224.0f + 1e-6f));
        lf = fminf(fmaxf(lf, 2.0f), 5.0f);
        const int L = (int)lf - 2;                    // 0..3
        const float scale = 0.25f / (float)(1 << L);  // exact powers of two
        const int   dim   = 40 >> L;
        const float dimf  = (float)dim;

        const float loC = __fmul_rn((d == 0 ? b0 : (d == 1 ? b1 : b2)), scale);
        const float hiC = __fmul_rn((d == 0 ? b3 : (d == 1 ? b4 : b5)), scale);
        const float len    = fmaxf(__fadd_rn(hiC, -loC), 1.0f);
        const float bin_sz = __fdiv_rn(len, 7.0f);
        const int   mult   = (d == 0) ? dim * dim : (d == 1 ? dim : 1);

        int   ids[4];
        float ws[4];
        int n = 0;
        #pragma unroll
        for (int smp = 0; smp < 2; ++smp) {
            const float pos = ((float)(2 * bin + smp) + 0.5f) * 0.5f;   // exact
            float c = __fadd_rn(loC, __fmul_rn(pos, bin_sz));
            const float valid = (c > -1.0f && c < dimf) ? 1.0f : 0.0f;
            c = fminf(fmaxf(c, 0.0f), dimf - 1.0f);
            const float low = floorf(c);
            const int   li  = (int)low;
            const int   hi  = min(li + 1, dim - 1);
            const float fr  = c - low;
            const float w_hi = fr * valid;
            const float w_lo = (1.0f - fr) * valid;

            int   pi[2] = {li, hi};
            float pw[2] = {w_lo, w_hi};
            #pragma unroll
            for (int q = 0; q < 2; ++q) {
                if (pw[q] == 0.0f) continue;       // dropping exact zeros is value-neutral
                bool found = false;
                for (int k = 0; k < n; ++k)
                    if (ids[k] == pi[q]) { ws[k] += pw[q]; found = true; break; }
                if (!found) { ids[n] = pi[q]; ws[n] = pw[q]; ++n; }
            }
        }
        s_cnt[d][bin] = n;
        #pragma unroll
        for (int k = 0; k < 4; ++k) {
            s_idx[d][bin][k] = (k < n) ? ids[k] * mult : 0;
            s_w  [d][bin][k] = (k < n) ? ws[k]         : 0.0f;
        }

        if (t == 0) {
            const float* f = (L == 0) ? x0 : (L == 1) ? x1 : (L == 2) ? x2 : x3;
            const int spat = dim * dim * dim;
            const int b    = roi / nb;
            s_base = f + (size_t)b * NCH * spat;
            s_lvl  = L;
        }
    }
    __syncthreads();

    if (t >= VOX) return;

    const int px = t % 7;
    const int py = (t / 7) % 7;
    const int pz = t / 49;

    // Load tap tables into registers (static indexing)
    int   zo[4], yo[4], xo[4];
    float zw[4], yw[4], xw[4];
    #pragma unroll
    for (int k = 0; k < 4; ++k) {
        zo[k] = s_idx[0][pz][k]; zw[k] = s_w[0][pz][k];
        yo[k] = s_idx[1][py][k]; yw[k] = s_w[1][py][k];
        xo[k] = s_idx[2][px][k]; xw[k] = s_w[2][px][k];
    }
    const int nz = s_cnt[0][pz];
    const int ny = s_cnt[1][py];
    const int nx = s_cnt[2][px];
    const int lvl = s_lvl;

    const float* __restrict__ sbase = s_base;
    float* __restrict__ op = out + ((size_t)roi * NCH + (size_t)cg * CG_SZ) * VOX + t;

    // Compile-time SPAT per level: channel offsets become LDG immediate
    // offsets, killing per-tap 64-bit address arithmetic.
#define BODY(SPATC)                                                             \
    {                                                                           \
        constexpr int SP = (SPATC);                                             \
        const float* __restrict__ base = sbase + (size_t)(cg * CG_SZ) * SP;     \
        _Pragma("unroll 1")                                                     \
        for (int cc = 0; cc < CG_SZ; cc += 4) {                                 \
            const float* __restrict__ p = base + (size_t)cc * SP;               \
            float a0 = 0.0f, a1 = 0.0f, a2 = 0.0f, a3 = 0.0f;                   \
            _Pragma("unroll")                                                   \
            for (int iz = 0; iz < 4; ++iz) {                                    \
                if (iz >= nz) break;                                            \
                const float* pzp = p + zo[iz];                                  \
                const float wzv  = zw[iz];                                      \
                _Pragma("unroll")                                               \
                for (int iy = 0; iy < 4; ++iy) {                                \
                    if (iy >= ny) break;                                        \
                    const float* pyp = pzp + yo[iy];                            \
                    const float wzy  = wzv * yw[iy];                            \
                    float s0 = 0.0f, s1 = 0.0f, s2 = 0.0f, s3 = 0.0f;           \
                    _Pragma("unroll")                                           \
                    for (int ix = 0; ix < 4; ++ix) {                            \
                        if (ix >= nx) break;                                    \
                        const float* q = pyp + xo[ix];                          \
                        const float w  = xw[ix];                                \
                        const float v0 = __ldg(q);                              \
                        const float v1 = __ldg(q + SP);                         \
                        const float v2 = __ldg(q + 2 * SP);                     \
                        const float v3 = __ldg(q + 3 * SP);                     \
                        s0 = fmaf(w, v0, s0);                                   \
                        s1 = fmaf(w, v1, s1);                                   \
                        s2 = fmaf(w, v2, s2);                                   \
                        s3 = fmaf(w, v3, s3);                                   \
                    }                                                           \
                    a0 = fmaf(wzy, s0, a0);                                     \
                    a1 = fmaf(wzy, s1, a1);                                     \
                    a2 = fmaf(wzy, s2, a2);                                     \
                    a3 = fmaf(wzy, s3, a3);                                     \
                }                                                               \
            }                                                                   \
            float* o = op + (size_t)cc * VOX;                                   \
            o[0]               = a0 * 0.125f;                                   \
            o[(size_t)VOX]     = a1 * 0.125f;                                   \
            o[(size_t)VOX * 2] = a2 * 0.125f;                                   \
            o[(size_t)VOX * 3] = a3 * 0.125f;                                   \
        }                                                                       \
    }

    switch (lvl) {
        case 0: BODY(64000); break;   // 40^3
        case 1: BODY(8000);  break;   // 20^3
        case 2: BODY(1000);  break;   // 10^3
        default: BODY(125);  break;   // 5^3
    }
#undef BODY
}

extern "C" void kernel_launch(void* const* d_in, const int* in_sizes, int n_in,
                              void* d_out, int out_size)
{
    const float* x0    = (const float*)d_in[0];
    const float* x1    = (const float*)d_in[1];
    const float* x2    = (const float*)d_in[2];
    const float* x3    = (const float*)d_in[3];
    const float* boxes = (const float*)d_in[4];
    float* out = (float*)d_out;

    const int nrois = in_sizes[4] / 6;                 // B * nb (=256)
    int B = in_sizes[0] / (NCH * 40 * 40 * 40);
    if (B < 1) B = 1;
    int nb = nrois / B;
    if (nb < 1) nb = 1;

    dim3 grid(nrois, NCH / CG_SZ);
    roi_pool_kernel<<<grid, 352>>>(x0, x1, x2, x3, boxes, out, nb);
}